// round 7
// baseline (speedup 1.0000x reference)
#include <cuda_runtime.h>
#include <math.h>

#define BATCH 16
#define H0 1024
#define W0 1024

// scratch: a1,b1 (16*512*512) a2,b2 (16*256*256) a3,b3 (16*128*128) a4,b4 (16*64*64)
#define N1 4194304
#define N2 1048576
#define N3 262144
#define N4 65536
__device__ float d_scratch[2 * (N1 + N2 + N3 + N4)];
__device__ double d_ssim_sum[5];
__device__ unsigned int d_max_bits;
__device__ float d_g1d[5];

__global__ void init_kernel(const float* __restrict__ window) {
    int t = threadIdx.x;
    if (t < 5) {
        float s = 0.f;
        #pragma unroll
        for (int j = 0; j < 5; ++j) s += window[t * 5 + j];
        d_g1d[t] = s;            // row sums of outer(g,g) recover g exactly
        d_ssim_sum[t] = 0.0;
    }
    if (t == 0) d_max_bits = 0u;
}

__global__ void max_kernel(const float* __restrict__ x, int n4) {
    int i = blockIdx.x * blockDim.x + threadIdx.x;
    const float4* x4 = (const float4*)x;
    float m = 0.f;  // inputs are uniform[0,1): non-negative
    for (int idx = i; idx < n4; idx += gridDim.x * blockDim.x) {
        float4 v = x4[idx];
        m = fmaxf(m, fmaxf(fmaxf(v.x, v.y), fmaxf(v.z, v.w)));
    }
    #pragma unroll
    for (int o = 16; o; o >>= 1) m = fmaxf(m, __shfl_xor_sync(0xffffffffu, m, o));
    if ((threadIdx.x & 31) == 0) atomicMax(&d_max_bits, __float_as_uint(m));
}

__device__ __forceinline__ float ssim_px(float mu1, float mu2, float s11, float s22, float s12) {
    const float C1 = 6.5025f;    // (0.01*255)^2
    const float C2 = 58.5225f;   // (0.03*255)^2
    float mu1sq = mu1 * mu1, mu2sq = mu2 * mu2, mu12 = mu1 * mu2;
    float sig1 = s11 - mu1sq, sig2 = s22 - mu2sq, sig12 = s12 - mu12;
    float num = (2.f * mu12 + C1) * (2.f * sig12 + C2);
    float den = (mu1sq + mu2sq + C1) * (sig1 + sig2 + C2);
    return num / den;
}

// Fused per-level kernel. For DIL<=2 (levels 0,1): paired outputs share conv taps
// (6 taps for 2 outputs instead of 10), and NT=512 threads lift occupancy to the
// 64-warp cap. Levels 2-4 keep the proven unpaired path.
template <int DIL, int TILE, int NT, bool LEVEL0, bool DO_POOL>
__global__ void __launch_bounds__(NT)
ssim_kernel(const float* __restrict__ A, const float* __restrict__ B,
            float* __restrict__ PA, float* __restrict__ PB,
            int H, int W, int level) {
    constexpr int R  = 2 * DIL;
    constexpr int LW = TILE + 4 * DIL;
    constexpr int LH = TILE + 4 * DIL;
    constexpr int TSH = (TILE == 32) ? 5 : 4;
    constexpr bool PAIRED = (DIL <= 2) && (TILE == 32);

    __shared__ __align__(8)  float2 sab[LH * LW];
    __shared__ __align__(16) float4 svA[TILE * LW];
    __shared__ float svB[TILE * LW];
    __shared__ float warp_sums[NT / 32];

    const int tid = threadIdx.x;
    const int x0 = blockIdx.x * TILE;
    const int y0 = blockIdx.y * TILE;
    const int base = blockIdx.z * H * W;   // 32-bit: max 16.7M elements

    float scale = 1.f;
    if (LEVEL0) {
        float m = __uint_as_float(d_max_bits);
        scale = 255.0f / (m + 1e-12f);
    }
    float g[5];
    #pragma unroll
    for (int k = 0; k < 5; ++k) g[k] = d_g1d[k];

    // ---- load tile + halo (zero padded), flat index, interleaved store ----
    for (int idx = tid; idx < LH * LW; idx += NT) {
        int ly = idx / LW, lx = idx - ly * LW;
        int gy = y0 - R + ly, gx = x0 - R + lx;
        float va = 0.f, vb = 0.f;
        if (gy >= 0 && gy < H && gx >= 0 && gx < W) {
            int o = base + gy * W + gx;
            va = A[o];
            vb = B[o];
            if (LEVEL0) { va = (va + 1e-12f) * scale; vb = (vb + 1e-12f) * scale; }
        }
        sab[idx] = make_float2(va, vb);
    }
    __syncthreads();

    // ---- vertical conv of 5 fields ----
    if (PAIRED) {
        // two output rows (r0, r0+DIL) per thread: 6 shared taps
        constexpr int NPV = (TILE / 2) * LW;
        for (int idx = tid; idx < NPV; idx += NT) {
            int rp = idx / LW, c = idx - rp * LW;
            int r0 = (DIL == 1) ? (2 * rp) : (((rp >> 1) << 2) + (rp & 1));
            float m1a = 0.f, m2a = 0.f, q11a = 0.f, q22a = 0.f, q12a = 0.f;
            float m1b = 0.f, m2b = 0.f, q11b = 0.f, q22b = 0.f, q12b = 0.f;
            #pragma unroll
            for (int k = 0; k < 6; ++k) {
                float2 v = sab[(r0 + k * DIL) * LW + c];
                float xx = v.x * v.x, yy = v.y * v.y, xy = v.x * v.y;
                if (k < 5) {
                    float w = g[k];
                    m1a += w * v.x; m2a += w * v.y;
                    q11a += w * xx; q22a += w * yy; q12a += w * xy;
                }
                if (k > 0) {
                    float w = g[k - 1];
                    m1b += w * v.x; m2b += w * v.y;
                    q11b += w * xx; q22b += w * yy; q12b += w * xy;
                }
            }
            int o0 = r0 * LW + c, o1 = o0 + DIL * LW;
            svA[o0] = make_float4(m1a, m2a, q11a, q22a); svB[o0] = q12a;
            svA[o1] = make_float4(m1b, m2b, q11b, q22b); svB[o1] = q12b;
        }
    } else {
        for (int idx = tid; idx < TILE * LW; idx += NT) {
            int r = idx / LW, c = idx - r * LW;
            float m1 = 0.f, m2 = 0.f, q11 = 0.f, q22 = 0.f, q12 = 0.f;
            #pragma unroll
            for (int k = 0; k < 5; ++k) {
                float2 v = sab[(r + k * DIL) * LW + c];
                float w = g[k];
                m1  += w * v.x;
                m2  += w * v.y;
                q11 += w * (v.x * v.x);
                q22 += w * (v.y * v.y);
                q12 += w * (v.x * v.y);
            }
            svA[idx] = make_float4(m1, m2, q11, q22);
            svB[idx] = q12;
        }
    }

    // ---- fused avg-pool (reads sab interior, unchanged since load sync) ----
    if (DO_POOL) {
        constexpr int PT = TILE / 2;
        constexpr int PTSH = (TILE == 32) ? 4 : 3;
        const int pW = W >> 1;
        const int pbase = blockIdx.z * (H >> 1) * pW;
        const int px0 = x0 >> 1, py0 = y0 >> 1;
        for (int idx = tid; idx < PT * PT; idx += NT) {
            int pr = idx >> PTSH, pc = idx & (PT - 1);
            int r = R + 2 * pr, c = R + 2 * pc;
            float2 v00 = sab[r * LW + c],       v01 = sab[r * LW + c + 1];
            float2 v10 = sab[(r + 1) * LW + c], v11 = sab[(r + 1) * LW + c + 1];
            int po = pbase + (py0 + pr) * pW + (px0 + pc);
            PA[po] = 0.25f * (v00.x + v01.x + v10.x + v11.x);
            PB[po] = 0.25f * (v00.y + v01.y + v10.y + v11.y);
        }
    }
    __syncthreads();

    // ---- horizontal conv + SSIM + reduce ----
    float lsum = 0.f;
    if (PAIRED) {
        // two output cols (c0, c0+DIL) per thread: 6 shared taps
        constexpr int NPH = TILE * (TILE / 2);
        for (int idx = tid; idx < NPH; idx += NT) {
            int r = idx >> 4;             // TILE/2 == 16 pairs per row
            int cp = idx & 15;
            int c0 = (DIL == 1) ? (2 * cp) : (((cp >> 1) << 2) + (cp & 1));
            const int ro = r * LW + c0;
            float mu1a = 0.f, mu2a = 0.f, s11a = 0.f, s22a = 0.f, s12a = 0.f;
            float mu1b = 0.f, mu2b = 0.f, s11b = 0.f, s22b = 0.f, s12b = 0.f;
            #pragma unroll
            for (int k = 0; k < 6; ++k) {
                int o = ro + k * DIL;
                float4 v = svA[o];
                float vb = svB[o];
                if (k < 5) {
                    float w = g[k];
                    mu1a += w * v.x; mu2a += w * v.y;
                    s11a += w * v.z; s22a += w * v.w; s12a += w * vb;
                }
                if (k > 0) {
                    float w = g[k - 1];
                    mu1b += w * v.x; mu2b += w * v.y;
                    s11b += w * v.z; s22b += w * v.w; s12b += w * vb;
                }
            }
            lsum += ssim_px(mu1a, mu2a, s11a, s22a, s12a);
            lsum += ssim_px(mu1b, mu2b, s11b, s22b, s12b);
        }
    } else {
        for (int idx = tid; idx < TILE * TILE; idx += NT) {
            int r = idx >> TSH, c = idx & (TILE - 1);
            const int ro = r * LW + c;
            float mu1 = 0.f, mu2 = 0.f, s11 = 0.f, s22 = 0.f, s12 = 0.f;
            #pragma unroll
            for (int k = 0; k < 5; ++k) {
                int o = ro + k * DIL;
                float w = g[k];
                float4 v = svA[o];
                mu1 += w * v.x;
                mu2 += w * v.y;
                s11 += w * v.z;
                s22 += w * v.w;
                s12 += w * svB[o];
            }
            lsum += ssim_px(mu1, mu2, s11, s22, s12);
        }
    }

    #pragma unroll
    for (int o = 16; o; o >>= 1) lsum += __shfl_xor_sync(0xffffffffu, lsum, o);
    if ((tid & 31) == 0) warp_sums[tid >> 5] = lsum;
    __syncthreads();
    if (tid == 0) {
        float s = 0.f;
        #pragma unroll
        for (int w = 0; w < NT / 32; ++w) s += warp_sums[w];
        atomicAdd(&d_ssim_sum[level], (double)s);
    }
}

__global__ void final_kernel(const float* __restrict__ weights, float* __restrict__ out) {
    if (threadIdx.x == 0) {
        double prod = 1.0;
        #pragma unroll
        for (int i = 0; i < 5; ++i) {
            double cnt = (double)BATCH * (double)(H0 >> i) * (double)(W0 >> i);
            double m = d_ssim_sum[i] / cnt;
            prod *= pow(m, (double)weights[i]);
        }
        out[0] = (float)(1.0 - prod);
    }
}

extern "C" void kernel_launch(void* const* d_in, const int* in_sizes, int n_in,
                              void* d_out, int out_size) {
    const float* img1    = (const float*)d_in[0];
    const float* img2    = (const float*)d_in[1];
    const float* window  = (const float*)d_in[2];
    const float* weights = (const float*)d_in[3];
    float* out = (float*)d_out;

    float* scratch;
    cudaGetSymbolAddress((void**)&scratch, d_scratch);
    float* a1 = scratch;      float* b1 = a1 + N1;
    float* a2 = b1 + N1;      float* b2 = a2 + N2;
    float* a3 = b2 + N2;      float* b3 = a3 + N3;
    float* a4 = b3 + N3;      float* b4 = a4 + N4;

    init_kernel<<<1, 32>>>(window);
    max_kernel<<<2048, 256>>>(img2, BATCH * H0 * W0 / 4);

    dim3 g0(W0 / 32, H0 / 32, BATCH);
    ssim_kernel<1, 32, 512, true,  true ><<<g0, 512>>>(img1, img2, a1, b1, 1024, 1024, 0);
    dim3 g1(512 / 32, 512 / 32, BATCH);
    ssim_kernel<2, 32, 512, false, true ><<<g1, 512>>>(a1, b1, a2, b2, 512, 512, 1);
    dim3 g2(256 / 32, 256 / 32, BATCH);
    ssim_kernel<3, 32, 512, false, true ><<<g2, 512>>>(a2, b2, a3, b3, 256, 256, 2);
    dim3 g3(128 / 16, 128 / 16, BATCH);
    ssim_kernel<6, 16, 256, false, true ><<<g3, 256>>>(a3, b3, a4, b4, 128, 128, 3);
    dim3 g4(64 / 16, 64 / 16, BATCH);
    ssim_kernel<9, 16, 256, false, false><<<g4, 256>>>(a4, b4, nullptr, nullptr, 64, 64, 4);

    final_kernel<<<1, 32>>>(weights, out);
}

// round 8
// speedup vs baseline: 1.0899x; 1.0899x over previous
#include <cuda_runtime.h>
#include <math.h>

#define BATCH 16
#define H0 1024
#define W0 1024

// scratch: a1,b1 (16*512*512) a2,b2 (16*256*256) a3,b3 (16*128*128) a4,b4 (16*64*64)
#define N1 4194304
#define N2 1048576
#define N3 262144
#define N4 65536
__device__ float d_scratch[2 * (N1 + N2 + N3 + N4)];
__device__ double d_ssim_sum[5];
__device__ unsigned int d_max_bits;
__device__ float d_g1d[5];

__global__ void init_kernel(const float* __restrict__ window) {
    int t = threadIdx.x;
    if (t < 5) {
        float s = 0.f;
        #pragma unroll
        for (int j = 0; j < 5; ++j) s += window[t * 5 + j];
        d_g1d[t] = s;            // row sums of outer(g,g) recover g exactly
        d_ssim_sum[t] = 0.0;
    }
    if (t == 0) d_max_bits = 0u;
}

__global__ void max_kernel(const float* __restrict__ x, int n4) {
    int i = blockIdx.x * blockDim.x + threadIdx.x;
    const float4* x4 = (const float4*)x;
    float m = 0.f;  // inputs are uniform[0,1): non-negative
    for (int idx = i; idx < n4; idx += gridDim.x * blockDim.x) {
        float4 v = x4[idx];
        m = fmaxf(m, fmaxf(fmaxf(v.x, v.y), fmaxf(v.z, v.w)));
    }
    #pragma unroll
    for (int o = 16; o; o >>= 1) m = fmaxf(m, __shfl_xor_sync(0xffffffffu, m, o));
    if ((threadIdx.x & 31) == 0) atomicMax(&d_max_bits, __float_as_uint(m));
}

__device__ __forceinline__ float ssim_px(float mu1, float mu2, float s11, float s22, float s12) {
    const float C1 = 6.5025f;    // (0.01*255)^2
    const float C2 = 58.5225f;   // (0.03*255)^2
    float mu1sq = mu1 * mu1, mu2sq = mu2 * mu2, mu12 = mu1 * mu2;
    float sig1 = s11 - mu1sq, sig2 = s22 - mu2sq, sig12 = s12 - mu12;
    float num = (2.f * mu12 + C1) * (2.f * sig12 + C2);
    float den = (mu1sq + mu2sq + C1) * (sig1 + sig2 + C2);
    return __fdividef(num, den);   // MUFU.RCP-based: ~4 instr vs ~20, ~2ulp
}

// Fused per-level kernel (round-6 structure: flat-index, vector-packed smem):
//   - loads a,b tile (+halo) as interleaved float2; interior blocks skip bounds checks
//   - vertical 5-tap dilated conv of {a,b,a2,b2,ab}: LDS.64 reads, STS.128+STS.32 writes
//   - fused 2x2 avg-pool of sab interior -> next-level buffers
//   - horizontal conv: LDS.128+LDS.32 reads + SSIM (fast divide) + block reduce
template <int DIL, int TILE, bool LEVEL0, bool DO_POOL>
__global__ void __launch_bounds__(256)
ssim_kernel(const float* __restrict__ A, const float* __restrict__ B,
            float* __restrict__ PA, float* __restrict__ PB,
            int H, int W, int level) {
    constexpr int R  = 2 * DIL;
    constexpr int LW = TILE + 4 * DIL;
    constexpr int LH = TILE + 4 * DIL;
    constexpr int TSH = (TILE == 32) ? 5 : 4;

    __shared__ __align__(8)  float2 sab[LH * LW];
    __shared__ __align__(16) float4 svA[TILE * LW];
    __shared__ float svB[TILE * LW];
    __shared__ float warp_sums[8];

    const int tid = threadIdx.x;
    const int x0 = blockIdx.x * TILE;
    const int y0 = blockIdx.y * TILE;
    const int base = blockIdx.z * H * W;   // 32-bit: max 16.7M elements

    float scale = 1.f;
    if (LEVEL0) {
        float m = __uint_as_float(d_max_bits);
        scale = 255.0f / (m + 1e-12f);
    }
    float g[5];
    #pragma unroll
    for (int k = 0; k < 5; ++k) g[k] = d_g1d[k];

    // ---- load tile + halo: interior blocks take an unpredicated fast path ----
    const bool interior = (x0 >= R) && (x0 + TILE + R <= W) &&
                          (y0 >= R) && (y0 + TILE + R <= H);
    if (interior) {
        const int org = base + (y0 - R) * W + (x0 - R);
        for (int idx = tid; idx < LH * LW; idx += 256) {
            int ly = idx / LW, lx = idx - ly * LW;
            int o = org + ly * W + lx;
            float va = A[o];
            float vb = B[o];
            if (LEVEL0) { va = (va + 1e-12f) * scale; vb = (vb + 1e-12f) * scale; }
            sab[idx] = make_float2(va, vb);
        }
    } else {
        for (int idx = tid; idx < LH * LW; idx += 256) {
            int ly = idx / LW, lx = idx - ly * LW;
            int gy = y0 - R + ly, gx = x0 - R + lx;
            float va = 0.f, vb = 0.f;
            if (gy >= 0 && gy < H && gx >= 0 && gx < W) {
                int o = base + gy * W + gx;
                va = A[o];
                vb = B[o];
                if (LEVEL0) { va = (va + 1e-12f) * scale; vb = (vb + 1e-12f) * scale; }
            }
            sab[idx] = make_float2(va, vb);
        }
    }
    __syncthreads();

    // ---- vertical conv of 5 fields: flat over TILE x LW, LDS.64 taps ----
    for (int idx = tid; idx < TILE * LW; idx += 256) {
        int r = idx / LW, c = idx - r * LW;
        float m1 = 0.f, m2 = 0.f, q11 = 0.f, q22 = 0.f, q12 = 0.f;
        #pragma unroll
        for (int k = 0; k < 5; ++k) {
            float2 v = sab[(r + k * DIL) * LW + c];
            float w = g[k];
            m1  += w * v.x;
            m2  += w * v.y;
            q11 += w * (v.x * v.x);
            q22 += w * (v.y * v.y);
            q12 += w * (v.x * v.y);
        }
        svA[idx] = make_float4(m1, m2, q11, q22);
        svB[idx] = q12;
    }

    // ---- fused avg-pool (reads sab interior, unchanged since load sync) ----
    if (DO_POOL) {
        constexpr int PT = TILE / 2;
        constexpr int PTSH = (TILE == 32) ? 4 : 3;
        const int pW = W >> 1;
        const int pbase = blockIdx.z * (H >> 1) * pW;
        const int px0 = x0 >> 1, py0 = y0 >> 1;
        for (int idx = tid; idx < PT * PT; idx += 256) {
            int pr = idx >> PTSH, pc = idx & (PT - 1);
            int r = R + 2 * pr, c = R + 2 * pc;
            float2 v00 = sab[r * LW + c],       v01 = sab[r * LW + c + 1];
            float2 v10 = sab[(r + 1) * LW + c], v11 = sab[(r + 1) * LW + c + 1];
            int po = pbase + (py0 + pr) * pW + (px0 + pc);
            PA[po] = 0.25f * (v00.x + v01.x + v10.x + v11.x);
            PB[po] = 0.25f * (v00.y + v01.y + v10.y + v11.y);
        }
    }
    __syncthreads();

    // ---- horizontal conv + SSIM + reduce: TILE x TILE outputs ----
    float lsum = 0.f;
    for (int idx = tid; idx < TILE * TILE; idx += 256) {
        int r = idx >> TSH, c = idx & (TILE - 1);
        const int ro = r * LW + c;
        float mu1 = 0.f, mu2 = 0.f, s11 = 0.f, s22 = 0.f, s12 = 0.f;
        #pragma unroll
        for (int k = 0; k < 5; ++k) {
            int o = ro + k * DIL;
            float w = g[k];
            float4 v = svA[o];
            mu1 += w * v.x;
            mu2 += w * v.y;
            s11 += w * v.z;
            s22 += w * v.w;
            s12 += w * svB[o];
        }
        lsum += ssim_px(mu1, mu2, s11, s22, s12);
    }

    #pragma unroll
    for (int o = 16; o; o >>= 1) lsum += __shfl_xor_sync(0xffffffffu, lsum, o);
    if ((tid & 31) == 0) warp_sums[tid >> 5] = lsum;
    __syncthreads();
    if (tid == 0) {
        float s = 0.f;
        #pragma unroll
        for (int w = 0; w < 8; ++w) s += warp_sums[w];
        atomicAdd(&d_ssim_sum[level], (double)s);
    }
}

__global__ void final_kernel(const float* __restrict__ weights, float* __restrict__ out) {
    if (threadIdx.x == 0) {
        double prod = 1.0;
        #pragma unroll
        for (int i = 0; i < 5; ++i) {
            double cnt = (double)BATCH * (double)(H0 >> i) * (double)(W0 >> i);
            double m = d_ssim_sum[i] / cnt;
            prod *= pow(m, (double)weights[i]);
        }
        out[0] = (float)(1.0 - prod);
    }
}

extern "C" void kernel_launch(void* const* d_in, const int* in_sizes, int n_in,
                              void* d_out, int out_size) {
    const float* img1    = (const float*)d_in[0];
    const float* img2    = (const float*)d_in[1];
    const float* window  = (const float*)d_in[2];
    const float* weights = (const float*)d_in[3];
    float* out = (float*)d_out;

    float* scratch;
    cudaGetSymbolAddress((void**)&scratch, d_scratch);
    float* a1 = scratch;      float* b1 = a1 + N1;
    float* a2 = b1 + N1;      float* b2 = a2 + N2;
    float* a3 = b2 + N2;      float* b3 = a3 + N3;
    float* a4 = b3 + N3;      float* b4 = a4 + N4;

    init_kernel<<<1, 32>>>(window);
    max_kernel<<<2048, 256>>>(img2, BATCH * H0 * W0 / 4);

    dim3 g0(W0 / 32, H0 / 32, BATCH);
    ssim_kernel<1, 32, true,  true ><<<g0, 256>>>(img1, img2, a1, b1, 1024, 1024, 0);
    dim3 g1(512 / 32, 512 / 32, BATCH);
    ssim_kernel<2, 32, false, true ><<<g1, 256>>>(a1, b1, a2, b2, 512, 512, 1);
    dim3 g2(256 / 32, 256 / 32, BATCH);
    ssim_kernel<3, 32, false, true ><<<g2, 256>>>(a2, b2, a3, b3, 256, 256, 2);
    dim3 g3(128 / 16, 128 / 16, BATCH);
    ssim_kernel<6, 16, false, true ><<<g3, 256>>>(a3, b3, a4, b4, 128, 128, 3);
    dim3 g4(64 / 16, 64 / 16, BATCH);
    ssim_kernel<9, 16, false, false><<<g4, 256>>>(a4, b4, nullptr, nullptr, 64, 64, 4);

    final_kernel<<<1, 32>>>(weights, out);
}

// round 11
// speedup vs baseline: 1.1391x; 1.0451x over previous
#include <cuda_runtime.h>
#include <math.h>

#define BATCH 16
#define H0 1024
#define W0 1024

// scratch: a1,b1 (16*512*512) a2,b2 (16*256*256) a3,b3 (16*128*128) a4,b4 (16*64*64)
#define N1 4194304
#define N2 1048576
#define N3 262144
#define N4 65536
__device__ float d_scratch[2 * (N1 + N2 + N3 + N4)];
__device__ double d_ssim_sum[5];
__device__ unsigned int d_max_bits;
__device__ float d_g1d[5];

__global__ void init_kernel(const float* __restrict__ window) {
    int t = threadIdx.x;
    if (t < 5) {
        float s = 0.f;
        #pragma unroll
        for (int j = 0; j < 5; ++j) s += window[t * 5 + j];
        d_g1d[t] = s;            // row sums of outer(g,g) recover g exactly
        d_ssim_sum[t] = 0.0;
    }
    if (t == 0) d_max_bits = 0u;
}

__global__ void max_kernel(const float* __restrict__ x, int n4) {
    int i = blockIdx.x * blockDim.x + threadIdx.x;
    const float4* x4 = (const float4*)x;
    float m = 0.f;  // inputs are uniform[0,1): non-negative
    for (int idx = i; idx < n4; idx += gridDim.x * blockDim.x) {
        float4 v = x4[idx];
        m = fmaxf(m, fmaxf(fmaxf(v.x, v.y), fmaxf(v.z, v.w)));
    }
    #pragma unroll
    for (int o = 16; o; o >>= 1) m = fmaxf(m, __shfl_xor_sync(0xffffffffu, m, o));
    if ((threadIdx.x & 31) == 0) atomicMax(&d_max_bits, __float_as_uint(m));
}

__device__ __forceinline__ float ssim_px(float mu1, float mu2, float s11, float s22, float s12) {
    const float C1 = 6.5025f;    // (0.01*255)^2
    const float C2 = 58.5225f;   // (0.03*255)^2
    float mu1sq = mu1 * mu1, mu2sq = mu2 * mu2, mu12 = mu1 * mu2;
    float sig1 = s11 - mu1sq, sig2 = s22 - mu2sq, sig12 = s12 - mu12;
    float num = (2.f * mu12 + C1) * (2.f * sig12 + C2);
    float den = (mu1sq + mu2sq + C1) * (sig1 + sig2 + C2);
    return __fdividef(num, den);   // MUFU.RCP-based: ~4 instr vs ~20, ~2ulp
}

// Fused per-level kernel:
//   - loads a,b tile (+halo) as interleaved float2; interior blocks skip bounds checks
//   - vertical 5-tap dilated conv of {a,b,a2,b2,ab} into 5 PLANAR smem arrays
//   - fused 2x2 avg-pool of sab interior -> next-level buffers
//   - horizontal conv: for TILE=32 & DIL<=2, each thread does 4 contiguous outputs
//     from 2-3 aligned LDS.128 per field (register tap reuse, conflict-free);
//     else scalar fallback. SSIM (fast divide) + block reduce -> double atomicAdd.
template <int DIL, int TILE, bool LEVEL0, bool DO_POOL>
__global__ void __launch_bounds__(256)
ssim_kernel(const float* __restrict__ A, const float* __restrict__ B,
            float* __restrict__ PA, float* __restrict__ PB,
            int H, int W, int level) {
    constexpr int R  = 2 * DIL;
    constexpr int LW = TILE + 4 * DIL;     // multiple of 4 for all levels
    constexpr int LH = TILE + 4 * DIL;
    constexpr int TSH = (TILE == 32) ? 5 : 4;
    constexpr bool VEC4 = (TILE == 32) && (DIL <= 2);

    __shared__ __align__(8)  float2 sab[LH * LW];
    __shared__ __align__(16) float sv[5][TILE * LW];
    __shared__ float warp_sums[8];

    const int tid = threadIdx.x;
    const int x0 = blockIdx.x * TILE;
    const int y0 = blockIdx.y * TILE;
    const int base = blockIdx.z * H * W;   // 32-bit: max 16.7M elements

    float scale = 1.f;
    if (LEVEL0) {
        float m = __uint_as_float(d_max_bits);
        scale = 255.0f / (m + 1e-12f);
    }
    float g[5];
    #pragma unroll
    for (int k = 0; k < 5; ++k) g[k] = d_g1d[k];

    // ---- load tile + halo: interior blocks take an unpredicated fast path ----
    const bool interior = (x0 >= R) && (x0 + TILE + R <= W) &&
                          (y0 >= R) && (y0 + TILE + R <= H);
    if (interior) {
        const int org = base + (y0 - R) * W + (x0 - R);
        for (int idx = tid; idx < LH * LW; idx += 256) {
            int ly = idx / LW, lx = idx - ly * LW;
            int o = org + ly * W + lx;
            float va = A[o];
            float vb = B[o];
            if (LEVEL0) { va = (va + 1e-12f) * scale; vb = (vb + 1e-12f) * scale; }
            sab[idx] = make_float2(va, vb);
        }
    } else {
        for (int idx = tid; idx < LH * LW; idx += 256) {
            int ly = idx / LW, lx = idx - ly * LW;
            int gy = y0 - R + ly, gx = x0 - R + lx;
            float va = 0.f, vb = 0.f;
            if (gy >= 0 && gy < H && gx >= 0 && gx < W) {
                int o = base + gy * W + gx;
                va = A[o];
                vb = B[o];
                if (LEVEL0) { va = (va + 1e-12f) * scale; vb = (vb + 1e-12f) * scale; }
            }
            sab[idx] = make_float2(va, vb);
        }
    }
    __syncthreads();

    // ---- vertical conv of 5 fields: flat over TILE x LW, LDS.64 taps ----
    for (int idx = tid; idx < TILE * LW; idx += 256) {
        int r = idx / LW, c = idx - r * LW;
        float m1 = 0.f, m2 = 0.f, q11 = 0.f, q22 = 0.f, q12 = 0.f;
        #pragma unroll
        for (int k = 0; k < 5; ++k) {
            float2 v = sab[(r + k * DIL) * LW + c];
            float w = g[k];
            m1  += w * v.x;
            m2  += w * v.y;
            q11 += w * (v.x * v.x);
            q22 += w * (v.y * v.y);
            q12 += w * (v.x * v.y);
        }
        sv[0][idx] = m1;  sv[1][idx] = m2;
        sv[2][idx] = q11; sv[3][idx] = q22; sv[4][idx] = q12;
    }

    // ---- fused avg-pool (reads sab interior, unchanged since load sync) ----
    if (DO_POOL) {
        constexpr int PT = TILE / 2;
        constexpr int PTSH = (TILE == 32) ? 4 : 3;
        const int pW = W >> 1;
        const int pbase = blockIdx.z * (H >> 1) * pW;
        const int px0 = x0 >> 1, py0 = y0 >> 1;
        for (int idx = tid; idx < PT * PT; idx += 256) {
            int pr = idx >> PTSH, pc = idx & (PT - 1);
            int r = R + 2 * pr, c = R + 2 * pc;
            float2 v00 = sab[r * LW + c],       v01 = sab[r * LW + c + 1];
            float2 v10 = sab[(r + 1) * LW + c], v11 = sab[(r + 1) * LW + c + 1];
            int po = pbase + (py0 + pr) * pW + (px0 + pc);
            PA[po] = 0.25f * (v00.x + v01.x + v10.x + v11.x);
            PB[po] = 0.25f * (v00.y + v01.y + v10.y + v11.y);
        }
    }
    __syncthreads();

    // ---- horizontal conv + SSIM + reduce ----
    float lsum = 0.f;
    if (VEC4) {
        // 4 contiguous outputs per thread: exactly 256 groups for TILE=32.
        // Taps span 4+4*DIL contiguous columns = NV aligned float4 loads per field.
        constexpr int NV = 1 + DIL;       // 2 (DIL=1) or 3 (DIL=2)
        const int r  = tid >> 3;          // output row 0..31
        const int c4 = tid & 7;           // float4 group 0..7 (columns 4*c4..4*c4+3)
        float acc[5][4];
        #pragma unroll
        for (int f = 0; f < 5; ++f) {
            const float4* rowp = (const float4*)(sv[f] + r * LW);
            float u[4 * NV];
            #pragma unroll
            for (int i = 0; i < NV; ++i) {
                float4 v = rowp[c4 + i];
                u[4 * i + 0] = v.x; u[4 * i + 1] = v.y;
                u[4 * i + 2] = v.z; u[4 * i + 3] = v.w;
            }
            #pragma unroll
            for (int j = 0; j < 4; ++j) {
                float a = 0.f;
                #pragma unroll
                for (int k = 0; k < 5; ++k) a += g[k] * u[j + k * DIL];
                acc[f][j] = a;
            }
        }
        #pragma unroll
        for (int j = 0; j < 4; ++j)
            lsum += ssim_px(acc[0][j], acc[1][j], acc[2][j], acc[3][j], acc[4][j]);
    } else {
        for (int idx = tid; idx < TILE * TILE; idx += 256) {
            int r = idx >> TSH, c = idx & (TILE - 1);
            const int ro = r * LW + c;
            float mu1 = 0.f, mu2 = 0.f, s11 = 0.f, s22 = 0.f, s12 = 0.f;
            #pragma unroll
            for (int k = 0; k < 5; ++k) {
                int o = ro + k * DIL;
                float w = g[k];
                mu1 += w * sv[0][o];
                mu2 += w * sv[1][o];
                s11 += w * sv[2][o];
                s22 += w * sv[3][o];
                s12 += w * sv[4][o];
            }
            lsum += ssim_px(mu1, mu2, s11, s22, s12);
        }
    }

    #pragma unroll
    for (int o = 16; o; o >>= 1) lsum += __shfl_xor_sync(0xffffffffu, lsum, o);
    if ((tid & 31) == 0) warp_sums[tid >> 5] = lsum;
    __syncthreads();
    if (tid == 0) {
        float s = 0.f;
        #pragma unroll
        for (int w = 0; w < 8; ++w) s += warp_sums[w];
        atomicAdd(&d_ssim_sum[level], (double)s);
    }
}

__global__ void final_kernel(const float* __restrict__ weights, float* __restrict__ out) {
    if (threadIdx.x == 0) {
        double prod = 1.0;
        #pragma unroll
        for (int i = 0; i < 5; ++i) {
            double cnt = (double)BATCH * (double)(H0 >> i) * (double)(W0 >> i);
            double m = d_ssim_sum[i] / cnt;
            prod *= pow(m, (double)weights[i]);
        }
        out[0] = (float)(1.0 - prod);
    }
}

extern "C" void kernel_launch(void* const* d_in, const int* in_sizes, int n_in,
                              void* d_out, int out_size) {
    const float* img1    = (const float*)d_in[0];
    const float* img2    = (const float*)d_in[1];
    const float* window  = (const float*)d_in[2];
    const float* weights = (const float*)d_in[3];
    float* out = (float*)d_out;

    float* scratch;
    cudaGetSymbolAddress((void**)&scratch, d_scratch);
    float* a1 = scratch;      float* b1 = a1 + N1;
    float* a2 = b1 + N1;      float* b2 = a2 + N2;
    float* a3 = b2 + N2;      float* b3 = a3 + N3;
    float* a4 = b3 + N3;      float* b4 = a4 + N4;

    init_kernel<<<1, 32>>>(window);
    max_kernel<<<2048, 256>>>(img2, BATCH * H0 * W0 / 4);

    dim3 g0(W0 / 32, H0 / 32, BATCH);
    ssim_kernel<1, 32, true,  true ><<<g0, 256>>>(img1, img2, a1, b1, 1024, 1024, 0);
    dim3 g1(512 / 32, 512 / 32, BATCH);
    ssim_kernel<2, 32, false, true ><<<g1, 256>>>(a1, b1, a2, b2, 512, 512, 1);
    dim3 g2(256 / 32, 256 / 32, BATCH);
    ssim_kernel<3, 32, false, true ><<<g2, 256>>>(a2, b2, a3, b3, 256, 256, 2);
    dim3 g3(128 / 16, 128 / 16, BATCH);
    ssim_kernel<6, 16, false, true ><<<g3, 256>>>(a3, b3, a4, b4, 128, 128, 3);
    dim3 g4(64 / 16, 64 / 16, BATCH);
    ssim_kernel<9, 16, false, false><<<g4, 256>>>(a4, b4, nullptr, nullptr, 64, 64, 4);

    final_kernel<<<1, 32>>>(weights, out);
}